// round 1
// baseline (speedup 1.0000x reference)
#include <cuda_runtime.h>

// Problem constants
#define R_DIM   16
#define C_SEQ   2048
#define E_DIM   256
#define H_NUM   8
#define D_DIM   512                 // R*hd
#define M_TOK   32768               // R*C
#define OUT_OFF 8388608ULL          // 16*2048*256 floats (out region size)
#define Q_SCALE 22.627416997969522f // sqrt(512)

// Scratch (static device globals: allocation-free per harness rules)
__device__ float g_q[H_NUM * C_SEQ * D_DIM];
__device__ float g_k[H_NUM * C_SEQ * D_DIM];
__device__ float g_v[H_NUM * C_SEQ * D_DIM];
__device__ float g_ctx[H_NUM * D_DIM * D_DIM];

// ---------------------------------------------------------------------------
// Shared tile loaders for the 128x128x16 fp32 GEMM core (256 threads)
// ---------------------------------------------------------------------------

// Operand stored [rows][K] (K-contiguous). Load 128 rows x 16 k, transposed
// into S[k][row].
__device__ __forceinline__ void load_nt(const float* __restrict__ P, int ld,
                                        int row0, int kt, float (*S)[128], int tid) {
    int lrow = tid >> 1;
    int lk   = (tid & 1) * 8;
    const float* src = P + (size_t)(row0 + lrow) * ld + kt + lk;
    float4 u0 = *(const float4*)(src);
    float4 u1 = *(const float4*)(src + 4);
    S[lk + 0][lrow] = u0.x; S[lk + 1][lrow] = u0.y;
    S[lk + 2][lrow] = u0.z; S[lk + 3][lrow] = u0.w;
    S[lk + 4][lrow] = u1.x; S[lk + 5][lrow] = u1.y;
    S[lk + 6][lrow] = u1.z; S[lk + 7][lrow] = u1.w;
}

// Operand stored [K][cols] (col-contiguous). Load 16 k-rows x 128 cols direct.
__device__ __forceinline__ void load_nn(const float* __restrict__ P, int ld,
                                        int col0, int kt, float (*S)[128], int tid) {
    int krow = tid >> 4;
    int cq   = (tid & 15) << 3;
    const float* src = P + (size_t)(kt + krow) * ld + col0 + cq;
    float4 u0 = *(const float4*)(src);
    float4 u1 = *(const float4*)(src + 4);
    *(float4*)&S[krow][cq]     = u0;
    *(float4*)&S[krow][cq + 4] = u1;
}

// 16-step rank-1 updates: each thread owns an 8x8 micro-tile.
__device__ __forceinline__ void mma_16(const float (*As)[128], const float (*Bs)[128],
                                       float acc[8][8], int ty, int tx) {
#pragma unroll
    for (int k = 0; k < 16; k++) {
        float4 a0 = *(const float4*)&As[k][ty * 8];
        float4 a1 = *(const float4*)&As[k][ty * 8 + 4];
        float4 b0 = *(const float4*)&Bs[k][tx * 8];
        float4 b1 = *(const float4*)&Bs[k][tx * 8 + 4];
        float av[8] = {a0.x, a0.y, a0.z, a0.w, a1.x, a1.y, a1.z, a1.w};
        float bv[8] = {b0.x, b0.y, b0.z, b0.w, b1.x, b1.y, b1.z, b1.w};
#pragma unroll
        for (int i = 0; i < 8; i++)
#pragma unroll
            for (int j = 0; j < 8; j++)
                acc[i][j] = fmaf(av[i], bv[j], acc[i][j]);
    }
}

// ---------------------------------------------------------------------------
// 1) Projections: q/k/v = x @ W^T + b, scattered into the _to_heads layout.
//    q_h[h'][c'][d'], h'=c>>8, c'=((c&255)<<3)|h, d'=(r<<5)|e
// grid (2, 256, 3), 256 threads
// ---------------------------------------------------------------------------
__global__ __launch_bounds__(256) void proj_kernel(
    const float* __restrict__ x,
    const float* __restrict__ Wq, const float* __restrict__ bq,
    const float* __restrict__ Wk, const float* __restrict__ bk,
    const float* __restrict__ Wv, const float* __restrict__ bv) {
    const float* W;
    const float* b;
    float* dst;
    if (blockIdx.z == 0)      { W = Wq; b = bq; dst = g_q; }
    else if (blockIdx.z == 1) { W = Wk; b = bk; dst = g_k; }
    else                      { W = Wv; b = bv; dst = g_v; }

    __shared__ float As[16][128];
    __shared__ float Bs[16][128];
    int tid = threadIdx.x;
    int ty = tid >> 4, tx = tid & 15;
    int m0 = blockIdx.y * 128, n0 = blockIdx.x * 128;

    float acc[8][8];
#pragma unroll
    for (int i = 0; i < 8; i++)
#pragma unroll
        for (int j = 0; j < 8; j++) acc[i][j] = 0.f;

    for (int kt = 0; kt < E_DIM; kt += 16) {
        load_nt(x, E_DIM, m0, kt, As, tid);
        load_nt(W, E_DIM, n0, kt, Bs, tid);
        __syncthreads();
        mma_16(As, Bs, acc, ty, tx);
        __syncthreads();
    }

#pragma unroll
    for (int i = 0; i < 8; i++) {
        int gi = m0 + ty * 8 + i;      // token index = r*2048 + c
        int r = gi >> 11;
        int c = gi & 2047;
        int hp = c >> 8;
        int cbase = (c & 255) << 3;
#pragma unroll
        for (int j = 0; j < 8; j++) {
            int gj = n0 + tx * 8 + j;  // feature = h*32 + e
            int h = gj >> 5, e = gj & 31;
            float val = acc[i][j] + b[gj];
            dst[((size_t)(hp * C_SEQ + (cbase | h))) * D_DIM + ((r << 5) | e)] = val;
        }
    }
}

// ---------------------------------------------------------------------------
// 2) Row softmax over d (512) on g_q, then scale by sqrt(512).
// grid 16384, 128 threads (float4 per thread)
// ---------------------------------------------------------------------------
__global__ __launch_bounds__(128) void softmax_q_kernel() {
    int row = blockIdx.x;
    float4* p = (float4*)(g_q + (size_t)row * D_DIM);
    int tid = threadIdx.x;
    float4 v = p[tid];

    float m = fmaxf(fmaxf(v.x, v.y), fmaxf(v.z, v.w));
#pragma unroll
    for (int o = 16; o; o >>= 1) m = fmaxf(m, __shfl_xor_sync(0xffffffffu, m, o));
    __shared__ float sm[4];
    __shared__ float ss[4];
    if ((tid & 31) == 0) sm[tid >> 5] = m;
    __syncthreads();
    m = fmaxf(fmaxf(sm[0], sm[1]), fmaxf(sm[2], sm[3]));

    v.x = __expf(v.x - m); v.y = __expf(v.y - m);
    v.z = __expf(v.z - m); v.w = __expf(v.w - m);
    float s = v.x + v.y + v.z + v.w;
#pragma unroll
    for (int o = 16; o; o >>= 1) s += __shfl_xor_sync(0xffffffffu, s, o);
    if ((tid & 31) == 0) ss[tid >> 5] = s;
    __syncthreads();
    s = ss[0] + ss[1] + ss[2] + ss[3];

    float f = Q_SCALE / s;
    v.x *= f; v.y *= f; v.z *= f; v.w *= f;
    p[tid] = v;
}

// ---------------------------------------------------------------------------
// 3) Column softmax over n (2048) on g_k, per (h, d').
// grid (16, 8), block (32, 8)
// ---------------------------------------------------------------------------
__global__ void softmax_k_kernel() {
    int h  = blockIdx.y;
    int d0 = blockIdx.x * 32;
    float* base = g_k + (size_t)h * C_SEQ * D_DIM + d0;
    int tx = threadIdx.x, ty = threadIdx.y;
    __shared__ float red[8][32];

    float m = -1e30f;
    for (int n = ty; n < C_SEQ; n += 8)
        m = fmaxf(m, base[(size_t)n * D_DIM + tx]);
    red[ty][tx] = m;
    __syncthreads();
    if (ty == 0) {
        float t = red[0][tx];
#pragma unroll
        for (int i = 1; i < 8; i++) t = fmaxf(t, red[i][tx]);
        red[0][tx] = t;
    }
    __syncthreads();
    m = red[0][tx];
    __syncthreads();

    float s = 0.f;
    for (int n = ty; n < C_SEQ; n += 8)
        s += __expf(base[(size_t)n * D_DIM + tx] - m);
    red[ty][tx] = s;
    __syncthreads();
    if (ty == 0) {
        float t = red[0][tx];
#pragma unroll
        for (int i = 1; i < 8; i++) t += red[i][tx];
        red[0][tx] = t;
    }
    __syncthreads();
    float inv = 1.f / red[0][tx];

    for (int n = ty; n < C_SEQ; n += 8) {
        size_t idx = (size_t)n * D_DIM + tx;
        base[idx] = __expf(base[idx] - m) * inv;
    }
}

// ---------------------------------------------------------------------------
// 4) attn[h] = q_s[h] (2048x512) @ k_s[h]^T -> [2048,2048]  (NT)
// grid (16, 16, 8), 256 threads
// ---------------------------------------------------------------------------
__global__ __launch_bounds__(256) void attn_kernel(float* __restrict__ outp) {
    int h = blockIdx.z;
    const float* A = g_q + (size_t)h * C_SEQ * D_DIM;
    const float* B = g_k + (size_t)h * C_SEQ * D_DIM;
    float* Cp = outp + OUT_OFF + (size_t)h * C_SEQ * C_SEQ;

    __shared__ float As[16][128];
    __shared__ float Bs[16][128];
    int tid = threadIdx.x;
    int ty = tid >> 4, tx = tid & 15;
    int m0 = blockIdx.y * 128, n0 = blockIdx.x * 128;

    float acc[8][8];
#pragma unroll
    for (int i = 0; i < 8; i++)
#pragma unroll
        for (int j = 0; j < 8; j++) acc[i][j] = 0.f;

    for (int kt = 0; kt < D_DIM; kt += 16) {
        load_nt(A, D_DIM, m0, kt, As, tid);
        load_nt(B, D_DIM, n0, kt, Bs, tid);
        __syncthreads();
        mma_16(As, Bs, acc, ty, tx);
        __syncthreads();
    }

#pragma unroll
    for (int i = 0; i < 8; i++) {
        float* dst = Cp + (size_t)(m0 + ty * 8 + i) * C_SEQ + n0 + tx * 8;
        *(float4*)(dst)     = make_float4(acc[i][0], acc[i][1], acc[i][2], acc[i][3]);
        *(float4*)(dst + 4) = make_float4(acc[i][4], acc[i][5], acc[i][6], acc[i][7]);
    }
}

// ---------------------------------------------------------------------------
// 5) ctx[h] = k_s[h]^T (512x2048) @ v[h] (2048x512) -> [512,512]  (TN)
// grid (4, 4, 8), 256 threads
// ---------------------------------------------------------------------------
__global__ __launch_bounds__(256) void ctx_kernel() {
    int h = blockIdx.z;
    const float* A = g_k + (size_t)h * C_SEQ * D_DIM;  // [n][d]
    const float* B = g_v + (size_t)h * C_SEQ * D_DIM;  // [n][e]
    float* Cp = g_ctx + (size_t)h * D_DIM * D_DIM;

    __shared__ float As[16][128];
    __shared__ float Bs[16][128];
    int tid = threadIdx.x;
    int ty = tid >> 4, tx = tid & 15;
    int d0 = blockIdx.y * 128, e0 = blockIdx.x * 128;

    float acc[8][8];
#pragma unroll
    for (int i = 0; i < 8; i++)
#pragma unroll
        for (int j = 0; j < 8; j++) acc[i][j] = 0.f;

    for (int kt = 0; kt < C_SEQ; kt += 16) {
        load_nn(A, D_DIM, d0, kt, As, tid);  // As[k][m] = k[n=kt+k][d0+m]
        load_nn(B, D_DIM, e0, kt, Bs, tid);
        __syncthreads();
        mma_16(As, Bs, acc, ty, tx);
        __syncthreads();
    }

#pragma unroll
    for (int i = 0; i < 8; i++) {
        float* dst = Cp + (size_t)(d0 + ty * 8 + i) * D_DIM + e0 + tx * 8;
        *(float4*)(dst)     = make_float4(acc[i][0], acc[i][1], acc[i][2], acc[i][3]);
        *(float4*)(dst + 4) = make_float4(acc[i][4], acc[i][5], acc[i][6], acc[i][7]);
    }
}

// ---------------------------------------------------------------------------
// 6) out[h] = q_s[h] (2048x512) @ ctx[h] (512x512) -> scatter into final view
//    final[r, c', h*32+e2] = out_h[h, c', r*32+e2]
// grid (4, 16, 8), 256 threads
// ---------------------------------------------------------------------------
__global__ __launch_bounds__(256) void out_kernel(float* __restrict__ outp) {
    int h = blockIdx.z;
    const float* A = g_q + (size_t)h * C_SEQ * D_DIM;    // [c'][d] trans-load
    const float* B = g_ctx + (size_t)h * D_DIM * D_DIM;  // [d][d''] direct-load

    __shared__ float As[16][128];
    __shared__ float Bs[16][128];
    int tid = threadIdx.x;
    int ty = tid >> 4, tx = tid & 15;
    int m0 = blockIdx.y * 128, n0 = blockIdx.x * 128;

    float acc[8][8];
#pragma unroll
    for (int i = 0; i < 8; i++)
#pragma unroll
        for (int j = 0; j < 8; j++) acc[i][j] = 0.f;

    for (int kt = 0; kt < D_DIM; kt += 16) {
        load_nt(A, D_DIM, m0, kt, As, tid);
        load_nn(B, D_DIM, n0, kt, Bs, tid);
        __syncthreads();
        mma_16(As, Bs, acc, ty, tx);
        __syncthreads();
    }

    int dpb = n0 + tx * 8;      // d' base; 8 contiguous stay within one r-block
    int r = dpb >> 5;
    int e2b = dpb & 31;
#pragma unroll
    for (int i = 0; i < 8; i++) {
        int cp = m0 + ty * 8 + i;
        float* dst = outp + (size_t)r * (C_SEQ * E_DIM) + (size_t)cp * E_DIM + h * 32 + e2b;
        *(float4*)(dst)     = make_float4(acc[i][0], acc[i][1], acc[i][2], acc[i][3]);
        *(float4*)(dst + 4) = make_float4(acc[i][4], acc[i][5], acc[i][6], acc[i][7]);
    }
}

// ---------------------------------------------------------------------------

extern "C" void kernel_launch(void* const* d_in, const int* in_sizes, int n_in,
                              void* d_out, int out_size) {
    const float* x  = (const float*)d_in[0];
    const float* Wq = (const float*)d_in[1];
    const float* bq = (const float*)d_in[2];
    const float* Wk = (const float*)d_in[3];
    const float* bk = (const float*)d_in[4];
    const float* Wv = (const float*)d_in[5];
    const float* bv = (const float*)d_in[6];
    float* out = (float*)d_out;

    proj_kernel<<<dim3(2, 256, 3), 256>>>(x, Wq, bq, Wk, bk, Wv, bv);
    softmax_q_kernel<<<H_NUM * C_SEQ, 128>>>();
    softmax_k_kernel<<<dim3(16, 8), dim3(32, 8)>>>();
    attn_kernel<<<dim3(16, 16, 8), 256>>>(out);
    ctx_kernel<<<dim3(4, 4, 8), 256>>>();
    out_kernel<<<dim3(4, 16, 8), 256>>>(out);
}

// round 5
// speedup vs baseline: 1.2983x; 1.2983x over previous
#include <cuda_runtime.h>
#include <cuda_bf16.h>
#include <cstdint>

// Problem constants
#define C_SEQ   2048
#define E_DIM   256
#define H_NUM   8
#define D_DIM   512                 // R*hd
#define OUT_OFF 8388608ULL          // 16*2048*256 floats (out region size)
#define Q_SCALE 22.627416997969522f // sqrt(512)

// ---------------------------------------------------------------------------
// Device scratch
// ---------------------------------------------------------------------------
__device__ float g_q[H_NUM * C_SEQ * D_DIM];
__device__ float g_k[H_NUM * C_SEQ * D_DIM];
__device__ float g_v[H_NUM * C_SEQ * D_DIM];
__device__ float g_ctx[H_NUM * D_DIM * D_DIM];

__device__ __align__(16) __nv_bfloat16 g_qh[H_NUM * C_SEQ * D_DIM];
__device__ __align__(16) __nv_bfloat16 g_ql[H_NUM * C_SEQ * D_DIM];
__device__ __align__(16) __nv_bfloat16 g_kh[H_NUM * C_SEQ * D_DIM];
__device__ __align__(16) __nv_bfloat16 g_kl[H_NUM * C_SEQ * D_DIM];

// ---------------------------------------------------------------------------
// fp32 SIMT GEMM pieces (PROVEN in R1 — verbatim)
// ---------------------------------------------------------------------------
__device__ __forceinline__ void load_nt(const float* __restrict__ P, int ld,
                                        int row0, int kt, float (*S)[128], int tid) {
    int lrow = tid >> 1;
    int lk   = (tid & 1) * 8;
    const float* src = P + (size_t)(row0 + lrow) * ld + kt + lk;
    float4 u0 = *(const float4*)(src);
    float4 u1 = *(const float4*)(src + 4);
    S[lk + 0][lrow] = u0.x; S[lk + 1][lrow] = u0.y;
    S[lk + 2][lrow] = u0.z; S[lk + 3][lrow] = u0.w;
    S[lk + 4][lrow] = u1.x; S[lk + 5][lrow] = u1.y;
    S[lk + 6][lrow] = u1.z; S[lk + 7][lrow] = u1.w;
}

__device__ __forceinline__ void load_nn(const float* __restrict__ P, int ld,
                                        int col0, int kt, float (*S)[128], int tid) {
    int krow = tid >> 4;
    int cq   = (tid & 15) << 3;
    const float* src = P + (size_t)(kt + krow) * ld + col0 + cq;
    float4 u0 = *(const float4*)(src);
    float4 u1 = *(const float4*)(src + 4);
    *(float4*)&S[krow][cq]     = u0;
    *(float4*)&S[krow][cq + 4] = u1;
}

__device__ __forceinline__ void mma_16(const float (*As)[128], const float (*Bs)[128],
                                       float acc[8][8], int ty, int tx) {
#pragma unroll
    for (int k = 0; k < 16; k++) {
        float4 a0 = *(const float4*)&As[k][ty * 8];
        float4 a1 = *(const float4*)&As[k][ty * 8 + 4];
        float4 b0 = *(const float4*)&Bs[k][tx * 8];
        float4 b1 = *(const float4*)&Bs[k][tx * 8 + 4];
        float av[8] = {a0.x, a0.y, a0.z, a0.w, a1.x, a1.y, a1.z, a1.w};
        float bv[8] = {b0.x, b0.y, b0.z, b0.w, b1.x, b1.y, b1.z, b1.w};
#pragma unroll
        for (int i = 0; i < 8; i++)
#pragma unroll
            for (int j = 0; j < 8; j++)
                acc[i][j] = fmaf(av[i], bv[j], acc[i][j]);
    }
}

// 1) Projections (R1-proven)
__global__ __launch_bounds__(256) void proj_kernel(
    const float* __restrict__ x,
    const float* __restrict__ Wq, const float* __restrict__ bq,
    const float* __restrict__ Wk, const float* __restrict__ bk,
    const float* __restrict__ Wv, const float* __restrict__ bv) {
    const float* W;
    const float* b;
    float* dst;
    if (blockIdx.z == 0)      { W = Wq; b = bq; dst = g_q; }
    else if (blockIdx.z == 1) { W = Wk; b = bk; dst = g_k; }
    else                      { W = Wv; b = bv; dst = g_v; }

    __shared__ float As[16][128];
    __shared__ float Bs[16][128];
    int tid = threadIdx.x;
    int ty = tid >> 4, tx = tid & 15;
    int m0 = blockIdx.y * 128, n0 = blockIdx.x * 128;

    float acc[8][8];
#pragma unroll
    for (int i = 0; i < 8; i++)
#pragma unroll
        for (int j = 0; j < 8; j++) acc[i][j] = 0.f;

    for (int kt = 0; kt < E_DIM; kt += 16) {
        load_nt(x, E_DIM, m0, kt, As, tid);
        load_nt(W, E_DIM, n0, kt, Bs, tid);
        __syncthreads();
        mma_16(As, Bs, acc, ty, tx);
        __syncthreads();
    }

#pragma unroll
    for (int i = 0; i < 8; i++) {
        int gi = m0 + ty * 8 + i;
        int r = gi >> 11;
        int c = gi & 2047;
        int hp = c >> 8;
        int cbase = (c & 255) << 3;
#pragma unroll
        for (int j = 0; j < 8; j++) {
            int gj = n0 + tx * 8 + j;
            int h = gj >> 5, e = gj & 31;
            float val = acc[i][j] + b[gj];
            dst[((size_t)(hp * C_SEQ + (cbase | h))) * D_DIM + ((r << 5) | e)] = val;
        }
    }
}

__device__ __forceinline__ void split_bf16(float x, __nv_bfloat16& h, __nv_bfloat16& l) {
    h = __float2bfloat16_rn(x);
    l = __float2bfloat16_rn(x - __bfloat162float(h));
}

// 2) Row softmax on q (R1-proven) + bf16 hi/lo tail
__global__ __launch_bounds__(128) void softmax_q_kernel() {
    size_t row = blockIdx.x;
    float4* p = (float4*)(g_q + row * D_DIM);
    int tid = threadIdx.x;
    float4 v = p[tid];

    float m = fmaxf(fmaxf(v.x, v.y), fmaxf(v.z, v.w));
#pragma unroll
    for (int o = 16; o; o >>= 1) m = fmaxf(m, __shfl_xor_sync(0xffffffffu, m, o));
    __shared__ float sm[4];
    __shared__ float ss[4];
    if ((tid & 31) == 0) sm[tid >> 5] = m;
    __syncthreads();
    m = fmaxf(fmaxf(sm[0], sm[1]), fmaxf(sm[2], sm[3]));

    v.x = __expf(v.x - m); v.y = __expf(v.y - m);
    v.z = __expf(v.z - m); v.w = __expf(v.w - m);
    float s = v.x + v.y + v.z + v.w;
#pragma unroll
    for (int o = 16; o; o >>= 1) s += __shfl_xor_sync(0xffffffffu, s, o);
    if ((tid & 31) == 0) ss[tid >> 5] = s;
    __syncthreads();
    s = ss[0] + ss[1] + ss[2] + ss[3];

    float f = Q_SCALE / s;
    v.x *= f; v.y *= f; v.z *= f; v.w *= f;
    p[tid] = v;   // fp32 writeback (for fp32 out-chain)

    float w[4] = {v.x, v.y, v.z, v.w};
    size_t base = row * D_DIM + tid * 4;
#pragma unroll
    for (int i = 0; i < 4; i++) {
        __nv_bfloat16 hi, lo;
        split_bf16(w[i], hi, lo);
        g_qh[base + i] = hi;
        g_ql[base + i] = lo;
    }
}

// 3) Column softmax on k (R1-proven) + bf16 hi/lo tail
__global__ void softmax_k_kernel() {
    int h  = blockIdx.y;
    int d0 = blockIdx.x * 32;
    size_t hoff = (size_t)h * C_SEQ * D_DIM;
    float* base = g_k + hoff + d0;
    int tx = threadIdx.x, ty = threadIdx.y;
    __shared__ float red[8][32];

    float m = -1e30f;
    for (int n = ty; n < C_SEQ; n += 8)
        m = fmaxf(m, base[(size_t)n * D_DIM + tx]);
    red[ty][tx] = m;
    __syncthreads();
    if (ty == 0) {
        float t = red[0][tx];
#pragma unroll
        for (int i = 1; i < 8; i++) t = fmaxf(t, red[i][tx]);
        red[0][tx] = t;
    }
    __syncthreads();
    m = red[0][tx];
    __syncthreads();

    float s = 0.f;
    for (int n = ty; n < C_SEQ; n += 8)
        s += __expf(base[(size_t)n * D_DIM + tx] - m);
    red[ty][tx] = s;
    __syncthreads();
    if (ty == 0) {
        float t = red[0][tx];
#pragma unroll
        for (int i = 1; i < 8; i++) t += red[i][tx];
        red[0][tx] = t;
    }
    __syncthreads();
    float inv = 1.f / red[0][tx];

    for (int n = ty; n < C_SEQ; n += 8) {
        size_t idx = (size_t)n * D_DIM + tx;
        float val = __expf(base[idx] - m) * inv;
        base[idx] = val;   // fp32 writeback (for fp32 ctx-chain)
        __nv_bfloat16 hi, lo;
        split_bf16(val, hi, lo);
        g_kh[hoff + d0 + idx] = hi;
        g_kl[hoff + d0 + idx] = lo;
    }
}

// ---------------------------------------------------------------------------
// MMA path (attn only): static SMEM, no cp.async, no dynamic config.
// ---------------------------------------------------------------------------
__device__ __forceinline__ uint32_t smem_to_u32(const void* p) {
    uint32_t a;
    asm("{ .reg .u64 t; cvta.to.shared.u64 t, %1; cvt.u32.u64 %0, t; }" : "=r"(a) : "l"(p));
    return a;
}
__device__ __forceinline__ void ldsm4(uint32_t r[4], uint32_t addr) {
    asm volatile("ldmatrix.sync.aligned.m8n8.x4.shared.b16 {%0,%1,%2,%3}, [%4];"
        : "=r"(r[0]), "=r"(r[1]), "=r"(r[2]), "=r"(r[3]) : "r"(addr));
}
__device__ __forceinline__ void mma16816(float d[4], const uint32_t a[4], const uint32_t b[2]) {
    asm volatile(
        "mma.sync.aligned.m16n8k16.row.col.f32.bf16.bf16.f32 "
        "{%0,%1,%2,%3}, {%4,%5,%6,%7}, {%8,%9}, {%0,%1,%2,%3};"
        : "+f"(d[0]), "+f"(d[1]), "+f"(d[2]), "+f"(d[3])
        : "r"(a[0]), "r"(a[1]), "r"(a[2]), "r"(a[3]), "r"(b[0]), "r"(b[1]));
}

#define ROW_STR    48                  // 16 bf16 (32B) padded to 48B, 16B-aligned
#define TILE_BYTES (128 * ROW_STR)     // 6144

// 5) attn[h] = q_s @ k_s^T via hi/lo bf16 HMMA.  grid (16,16,8), 256 thr.
//    Static SMEM: 4 tiles (Ah, Al, Bh, Bl) = 24576 B. Sync per K-chunk of 16.
__global__ __launch_bounds__(256) void attn_mma_kernel(float* __restrict__ outp) {
    __shared__ __align__(16) char smem[4 * TILE_BYTES];
    int h = blockIdx.z;
    int m0 = blockIdx.y * 128, n0 = blockIdx.x * 128;
    size_t hoff = (size_t)h * C_SEQ * D_DIM;
    const __nv_bfloat16* Ah = g_qh + hoff;
    const __nv_bfloat16* Al = g_ql + hoff;
    const __nv_bfloat16* Bh = g_kh + hoff;
    const __nv_bfloat16* Bl = g_kl + hoff;

    int tid = threadIdx.x;
    int lane = tid & 31;
    int wid = tid >> 5;
    int wm = wid >> 1, wn = wid & 1;
    uint32_t sb = smem_to_u32(smem);

    float acc[2][8][4];
#pragma unroll
    for (int mt = 0; mt < 2; mt++)
#pragma unroll
        for (int nt = 0; nt < 8; nt++)
#pragma unroll
            for (int f = 0; f < 4; f++) acc[mt][nt][f] = 0.f;

    int row = tid >> 1;            // 0..127
    int seg = tid & 1;             // 16B halves of the 32B row
    uint32_t so = row * ROW_STR + seg * 16;

    for (int kt = 0; kt < D_DIM; kt += 16) {
        // synchronous global -> shared (uint4)
        size_t ao = (size_t)(m0 + row) * D_DIM + kt + seg * 8;
        size_t bo = (size_t)(n0 + row) * D_DIM + kt + seg * 8;
        uint4 a_h = *(const uint4*)(Ah + ao);
        uint4 a_l = *(const uint4*)(Al + ao);
        uint4 b_h = *(const uint4*)(Bh + bo);
        uint4 b_l = *(const uint4*)(Bl + bo);
        *(uint4*)(smem + so)                  = a_h;
        *(uint4*)(smem + TILE_BYTES + so)     = a_l;
        *(uint4*)(smem + 2 * TILE_BYTES + so) = b_h;
        *(uint4*)(smem + 3 * TILE_BYTES + so) = b_l;
        __syncthreads();

        uint32_t ah[2][4], al[2][4];
#pragma unroll
        for (int mt = 0; mt < 2; mt++) {
            uint32_t mrow = wm * 32 + mt * 16 + (lane & 15);
            uint32_t co = (uint32_t)(lane >> 4) << 4;   // 0 or 16 B (k0-7 / k8-15)
            ldsm4(ah[mt], sb + mrow * ROW_STR + co);
            ldsm4(al[mt], sb + TILE_BYTES + mrow * ROW_STR + co);
        }
#pragma unroll
        for (int nt2 = 0; nt2 < 4; nt2++) {
            uint32_t brow = wn * 64 + nt2 * 16 + (lane & 7) + ((lane >> 4) << 3);
            uint32_t co = (uint32_t)((lane >> 3) & 1) << 4;
            uint32_t bh[4], bl[4];
            ldsm4(bh, sb + 2 * TILE_BYTES + brow * ROW_STR + co);
            ldsm4(bl, sb + 3 * TILE_BYTES + brow * ROW_STR + co);
#pragma unroll
            for (int mt = 0; mt < 2; mt++) {
#pragma unroll
                for (int hf = 0; hf < 2; hf++) {
                    int nt = nt2 * 2 + hf;
                    mma16816(acc[mt][nt], ah[mt], bh + hf * 2);
                    mma16816(acc[mt][nt], ah[mt], bl + hf * 2);
                    mma16816(acc[mt][nt], al[mt], bh + hf * 2);
                }
            }
        }
        __syncthreads();
    }

    float* Cp = outp + OUT_OFF + (size_t)h * C_SEQ * C_SEQ;
#pragma unroll
    for (int mt = 0; mt < 2; mt++) {
#pragma unroll
        for (int hf = 0; hf < 2; hf++) {
            int rr = m0 + wm * 32 + mt * 16 + (lane >> 2) + hf * 8;
            float* rowp = Cp + (size_t)rr * C_SEQ;
#pragma unroll
            for (int nt = 0; nt < 8; nt++) {
                int cc = n0 + wn * 64 + nt * 8 + ((lane & 3) << 1);
                *(float2*)(rowp + cc) = make_float2(acc[mt][nt][hf * 2], acc[mt][nt][hf * 2 + 1]);
            }
        }
    }
}

// 6) ctx[h] = k_s^T @ v (R1-proven fp32)
__global__ __launch_bounds__(256) void ctx_kernel() {
    int h = blockIdx.z;
    const float* A = g_k + (size_t)h * C_SEQ * D_DIM;
    const float* B = g_v + (size_t)h * C_SEQ * D_DIM;
    float* Cp = g_ctx + (size_t)h * D_DIM * D_DIM;

    __shared__ float As[16][128];
    __shared__ float Bs[16][128];
    int tid = threadIdx.x;
    int ty = tid >> 4, tx = tid & 15;
    int d0 = blockIdx.y * 128, e0 = blockIdx.x * 128;

    float acc[8][8];
#pragma unroll
    for (int i = 0; i < 8; i++)
#pragma unroll
        for (int j = 0; j < 8; j++) acc[i][j] = 0.f;

    for (int kt = 0; kt < C_SEQ; kt += 16) {
        load_nn(A, D_DIM, d0, kt, As, tid);
        load_nn(B, D_DIM, e0, kt, Bs, tid);
        __syncthreads();
        mma_16(As, Bs, acc, ty, tx);
        __syncthreads();
    }

#pragma unroll
    for (int i = 0; i < 8; i++) {
        float* dst = Cp + (size_t)(d0 + ty * 8 + i) * D_DIM + e0 + tx * 8;
        *(float4*)(dst)     = make_float4(acc[i][0], acc[i][1], acc[i][2], acc[i][3]);
        *(float4*)(dst + 4) = make_float4(acc[i][4], acc[i][5], acc[i][6], acc[i][7]);
    }
}

// 7) out[h] = q_s @ ctx (R1-proven fp32) -> scatter to final view
__global__ __launch_bounds__(256) void out_kernel(float* __restrict__ outp) {
    int h = blockIdx.z;
    const float* A = g_q + (size_t)h * C_SEQ * D_DIM;
    const float* B = g_ctx + (size_t)h * D_DIM * D_DIM;

    __shared__ float As[16][128];
    __shared__ float Bs[16][128];
    int tid = threadIdx.x;
    int ty = tid >> 4, tx = tid & 15;
    int m0 = blockIdx.y * 128, n0 = blockIdx.x * 128;

    float acc[8][8];
#pragma unroll
    for (int i = 0; i < 8; i++)
#pragma unroll
        for (int j = 0; j < 8; j++) acc[i][j] = 0.f;

    for (int kt = 0; kt < D_DIM; kt += 16) {
        load_nt(A, D_DIM, m0, kt, As, tid);
        load_nn(B, D_DIM, n0, kt, Bs, tid);
        __syncthreads();
        mma_16(As, Bs, acc, ty, tx);
        __syncthreads();
    }

    int dpb = n0 + tx * 8;
    int r = dpb >> 5;
    int e2b = dpb & 31;
#pragma unroll
    for (int i = 0; i < 8; i++) {
        int cp = m0 + ty * 8 + i;
        float* dst = outp + (size_t)r * (C_SEQ * E_DIM) + (size_t)cp * E_DIM + h * 32 + e2b;
        *(float4*)(dst)     = make_float4(acc[i][0], acc[i][1], acc[i][2], acc[i][3]);
        *(float4*)(dst + 4) = make_float4(acc[i][4], acc[i][5], acc[i][6], acc[i][7]);
    }
}

// ---------------------------------------------------------------------------

extern "C" void kernel_launch(void* const* d_in, const int* in_sizes, int n_in,
                              void* d_out, int out_size) {
    const float* x  = (const float*)d_in[0];
    const float* Wq = (const float*)d_in[1];
    const float* bq = (const float*)d_in[2];
    const float* Wk = (const float*)d_in[3];
    const float* bk = (const float*)d_in[4];
    const float* Wv = (const float*)d_in[5];
    const float* bv = (const float*)d_in[6];
    float* out = (float*)d_out;

    proj_kernel<<<dim3(2, 256, 3), 256>>>(x, Wq, bq, Wk, bk, Wv, bv);
    softmax_q_kernel<<<H_NUM * C_SEQ, 128>>>();
    softmax_k_kernel<<<dim3(16, 8), dim3(32, 8)>>>();
    attn_mma_kernel<<<dim3(16, 16, 8), 256>>>(out);
    ctx_kernel<<<dim3(4, 4, 8), 256>>>();
    out_kernel<<<dim3(4, 16, 8), 256>>>(out);
}

// round 8
// speedup vs baseline: 1.5984x; 1.2312x over previous
#include <cuda_runtime.h>
#include <cuda_bf16.h>
#include <cstdint>

// Problem constants
#define C_SEQ   2048
#define E_DIM   256
#define H_NUM   8
#define D_DIM   512                 // R*hd
#define OUT_OFF 8388608ULL          // 16*2048*256 floats (out region size)
#define Q_SCALE 22.627416997969522f // sqrt(512)

// ---------------------------------------------------------------------------
// Device scratch (no aliasing, no arena)
// ---------------------------------------------------------------------------
__device__ float g_q[H_NUM * C_SEQ * D_DIM];
__device__ float g_k[H_NUM * C_SEQ * D_DIM];
__device__ float g_v[H_NUM * C_SEQ * D_DIM];

__device__ __align__(16) __nv_bfloat16 g_qh[H_NUM * C_SEQ * D_DIM];
__device__ __align__(16) __nv_bfloat16 g_ql[H_NUM * C_SEQ * D_DIM];
__device__ __align__(16) __nv_bfloat16 g_kh[H_NUM * C_SEQ * D_DIM];
__device__ __align__(16) __nv_bfloat16 g_kl[H_NUM * C_SEQ * D_DIM];
__device__ __align__(16) __nv_bfloat16 g_kth[H_NUM * D_DIM * C_SEQ];
__device__ __align__(16) __nv_bfloat16 g_ktl[H_NUM * D_DIM * C_SEQ];
__device__ __align__(16) __nv_bfloat16 g_vth[H_NUM * D_DIM * C_SEQ];
__device__ __align__(16) __nv_bfloat16 g_vtl[H_NUM * D_DIM * C_SEQ];
__device__ __align__(16) __nv_bfloat16 g_cth[H_NUM * D_DIM * D_DIM];  // ctxT[e''][d]
__device__ __align__(16) __nv_bfloat16 g_ctl[H_NUM * D_DIM * D_DIM];

// ---------------------------------------------------------------------------
// fp32 SIMT GEMM pieces (R1-PROVEN — verbatim)
// ---------------------------------------------------------------------------
__device__ __forceinline__ void load_nt(const float* __restrict__ P, int ld,
                                        int row0, int kt, float (*S)[128], int tid) {
    int lrow = tid >> 1;
    int lk   = (tid & 1) * 8;
    const float* src = P + (size_t)(row0 + lrow) * ld + kt + lk;
    float4 u0 = *(const float4*)(src);
    float4 u1 = *(const float4*)(src + 4);
    S[lk + 0][lrow] = u0.x; S[lk + 1][lrow] = u0.y;
    S[lk + 2][lrow] = u0.z; S[lk + 3][lrow] = u0.w;
    S[lk + 4][lrow] = u1.x; S[lk + 5][lrow] = u1.y;
    S[lk + 6][lrow] = u1.z; S[lk + 7][lrow] = u1.w;
}

__device__ __forceinline__ void mma_16(const float (*As)[128], const float (*Bs)[128],
                                       float acc[8][8], int ty, int tx) {
#pragma unroll
    for (int k = 0; k < 16; k++) {
        float4 a0 = *(const float4*)&As[k][ty * 8];
        float4 a1 = *(const float4*)&As[k][ty * 8 + 4];
        float4 b0 = *(const float4*)&Bs[k][tx * 8];
        float4 b1 = *(const float4*)&Bs[k][tx * 8 + 4];
        float av[8] = {a0.x, a0.y, a0.z, a0.w, a1.x, a1.y, a1.z, a1.w};
        float bv[8] = {b0.x, b0.y, b0.z, b0.w, b1.x, b1.y, b1.z, b1.w};
#pragma unroll
        for (int i = 0; i < 8; i++)
#pragma unroll
            for (int j = 0; j < 8; j++)
                acc[i][j] = fmaf(av[i], bv[j], acc[i][j]);
    }
}

// 1) Projections (R1-proven, verbatim)
__global__ __launch_bounds__(256) void proj_kernel(
    const float* __restrict__ x,
    const float* __restrict__ Wq, const float* __restrict__ bq,
    const float* __restrict__ Wk, const float* __restrict__ bk,
    const float* __restrict__ Wv, const float* __restrict__ bv) {
    const float* W;
    const float* b;
    float* dst;
    if (blockIdx.z == 0)      { W = Wq; b = bq; dst = g_q; }
    else if (blockIdx.z == 1) { W = Wk; b = bk; dst = g_k; }
    else                      { W = Wv; b = bv; dst = g_v; }

    __shared__ float As[16][128];
    __shared__ float Bs[16][128];
    int tid = threadIdx.x;
    int ty = tid >> 4, tx = tid & 15;
    int m0 = blockIdx.y * 128, n0 = blockIdx.x * 128;

    float acc[8][8];
#pragma unroll
    for (int i = 0; i < 8; i++)
#pragma unroll
        for (int j = 0; j < 8; j++) acc[i][j] = 0.f;

    for (int kt = 0; kt < E_DIM; kt += 16) {
        load_nt(x, E_DIM, m0, kt, As, tid);
        load_nt(W, E_DIM, n0, kt, Bs, tid);
        __syncthreads();
        mma_16(As, Bs, acc, ty, tx);
        __syncthreads();
    }

#pragma unroll
    for (int i = 0; i < 8; i++) {
        int gi = m0 + ty * 8 + i;
        int r = gi >> 11;
        int c = gi & 2047;
        int hp = c >> 8;
        int cbase = (c & 255) << 3;
#pragma unroll
        for (int j = 0; j < 8; j++) {
            int gj = n0 + tx * 8 + j;
            int h = gj >> 5, e = gj & 31;
            float val = acc[i][j] + b[gj];
            dst[((size_t)(hp * C_SEQ + (cbase | h))) * D_DIM + ((r << 5) | e)] = val;
        }
    }
}

__device__ __forceinline__ void split_bf16(float x, __nv_bfloat16& h, __nv_bfloat16& l) {
    h = __float2bfloat16_rn(x);
    l = __float2bfloat16_rn(x - __bfloat162float(h));
}

// 2) Row softmax on q (R5-proven, verbatim)
__global__ __launch_bounds__(128) void softmax_q_kernel() {
    size_t row = blockIdx.x;
    float4* p = (float4*)(g_q + row * D_DIM);
    int tid = threadIdx.x;
    float4 v = p[tid];

    float m = fmaxf(fmaxf(v.x, v.y), fmaxf(v.z, v.w));
#pragma unroll
    for (int o = 16; o; o >>= 1) m = fmaxf(m, __shfl_xor_sync(0xffffffffu, m, o));
    __shared__ float sm[4];
    __shared__ float ss[4];
    if ((tid & 31) == 0) sm[tid >> 5] = m;
    __syncthreads();
    m = fmaxf(fmaxf(sm[0], sm[1]), fmaxf(sm[2], sm[3]));

    v.x = __expf(v.x - m); v.y = __expf(v.y - m);
    v.z = __expf(v.z - m); v.w = __expf(v.w - m);
    float s = v.x + v.y + v.z + v.w;
#pragma unroll
    for (int o = 16; o; o >>= 1) s += __shfl_xor_sync(0xffffffffu, s, o);
    if ((tid & 31) == 0) ss[tid >> 5] = s;
    __syncthreads();
    s = ss[0] + ss[1] + ss[2] + ss[3];

    float f = Q_SCALE / s;
    v.x *= f; v.y *= f; v.z *= f; v.w *= f;
    p[tid] = v;

    float w[4] = {v.x, v.y, v.z, v.w};
    size_t base = row * D_DIM + tid * 4;
#pragma unroll
    for (int i = 0; i < 4; i++) {
        __nv_bfloat16 hi, lo;
        split_bf16(w[i], hi, lo);
        g_qh[base + i] = hi;
        g_ql[base + i] = lo;
    }
}

// 3) Column softmax on k (R5-proven, verbatim)
__global__ void softmax_k_kernel() {
    int h  = blockIdx.y;
    int d0 = blockIdx.x * 32;
    size_t hoff = (size_t)h * C_SEQ * D_DIM;
    float* base = g_k + hoff + d0;
    int tx = threadIdx.x, ty = threadIdx.y;
    __shared__ float red[8][32];

    float m = -1e30f;
    for (int n = ty; n < C_SEQ; n += 8)
        m = fmaxf(m, base[(size_t)n * D_DIM + tx]);
    red[ty][tx] = m;
    __syncthreads();
    if (ty == 0) {
        float t = red[0][tx];
#pragma unroll
        for (int i = 1; i < 8; i++) t = fmaxf(t, red[i][tx]);
        red[0][tx] = t;
    }
    __syncthreads();
    m = red[0][tx];
    __syncthreads();

    float s = 0.f;
    for (int n = ty; n < C_SEQ; n += 8)
        s += __expf(base[(size_t)n * D_DIM + tx] - m);
    red[ty][tx] = s;
    __syncthreads();
    if (ty == 0) {
        float t = red[0][tx];
#pragma unroll
        for (int i = 1; i < 8; i++) t += red[i][tx];
        red[0][tx] = t;
    }
    __syncthreads();
    float inv = 1.f / red[0][tx];

    for (int n = ty; n < C_SEQ; n += 8) {
        size_t idx = (size_t)n * D_DIM + tx;
        float val = __expf(base[idx] - m) * inv;
        base[idx] = val;
        __nv_bfloat16 hi, lo;
        split_bf16(val, hi, lo);
        g_kh[hoff + d0 + idx] = hi;
        g_kl[hoff + d0 + idx] = lo;
    }
}

// ---------------------------------------------------------------------------
// 4) Transpose fp32 [h][2048][512] -> bf16 hi/lo [h][512][2048]
//    256-thread blocks (32 x 8). grid (16, 64, 16): z<8 -> k, z>=8 -> v.
// ---------------------------------------------------------------------------
__global__ __launch_bounds__(256) void transpose_hilo_kernel() {
    __shared__ float t[32][33];
    int z = blockIdx.z;
    int h = z & 7;
    const float* src = (z < 8) ? g_k : g_v;
    __nv_bfloat16* dh = (z < 8) ? g_kth : g_vth;
    __nv_bfloat16* dl = (z < 8) ? g_ktl : g_vtl;

    int d0 = blockIdx.x * 32;
    int n0 = blockIdx.y * 32;
    int tx = threadIdx.x, ty = threadIdx.y;
    const float* s = src + (size_t)h * C_SEQ * D_DIM;

#pragma unroll
    for (int i = 0; i < 4; i++) {
        int nn = ty + i * 8;
        t[nn][tx] = s[(size_t)(n0 + nn) * D_DIM + d0 + tx];  // t[n_local][d_local]
    }
    __syncthreads();
#pragma unroll
    for (int i = 0; i < 4; i++) {
        int dd = ty + i * 8;
        float val = t[tx][dd];                               // (n=n0+tx, d=d0+dd)
        __nv_bfloat16 hi, lo;
        split_bf16(val, hi, lo);
        size_t o = ((size_t)h * D_DIM + d0 + dd) * C_SEQ + n0 + tx;
        dh[o] = hi;
        dl[o] = lo;
    }
}

// ---------------------------------------------------------------------------
// hi/lo bf16 HMMA GEMM core (R5-PROVEN — verbatim, no prefetch).
// C(128x128) = A(128xK) . B(128xK)^T, K-major operands.
// ---------------------------------------------------------------------------
__device__ __forceinline__ uint32_t smem_to_u32(const void* p) {
    uint32_t a;
    asm("{ .reg .u64 t; cvta.to.shared.u64 t, %1; cvt.u32.u64 %0, t; }" : "=r"(a) : "l"(p));
    return a;
}
__device__ __forceinline__ void ldsm4(uint32_t r[4], uint32_t addr) {
    asm volatile("ldmatrix.sync.aligned.m8n8.x4.shared.b16 {%0,%1,%2,%3}, [%4];"
        : "=r"(r[0]), "=r"(r[1]), "=r"(r[2]), "=r"(r[3]) : "r"(addr));
}
__device__ __forceinline__ void mma16816(float d[4], const uint32_t a[4], const uint32_t b[2]) {
    asm volatile(
        "mma.sync.aligned.m16n8k16.row.col.f32.bf16.bf16.f32 "
        "{%0,%1,%2,%3}, {%4,%5,%6,%7}, {%8,%9}, {%0,%1,%2,%3};"
        : "+f"(d[0]), "+f"(d[1]), "+f"(d[2]), "+f"(d[3])
        : "r"(a[0]), "r"(a[1]), "r"(a[2]), "r"(a[3]), "r"(b[0]), "r"(b[1]));
}

#define ROW_STR    48
#define TILE_BYTES (128 * ROW_STR)   // 6144
#define CORE_SMEM  (4 * TILE_BYTES)  // 24576

__device__ __forceinline__ void gemm_hilo_core(
    float acc[2][8][4],
    const __nv_bfloat16* __restrict__ Ah, const __nv_bfloat16* __restrict__ Al,
    int lda, int m0,
    const __nv_bfloat16* __restrict__ Bh, const __nv_bfloat16* __restrict__ Bl,
    int ldb, int n0,
    int K, char* smem) {
    int tid = threadIdx.x;
    int lane = tid & 31;
    int wid = tid >> 5;
    int wm = wid >> 1, wn = wid & 1;
    uint32_t sb = smem_to_u32(smem);

#pragma unroll
    for (int mt = 0; mt < 2; mt++)
#pragma unroll
        for (int nt = 0; nt < 8; nt++)
#pragma unroll
            for (int f = 0; f < 4; f++) acc[mt][nt][f] = 0.f;

    int row = tid >> 1;
    int seg = tid & 1;
    uint32_t so = row * ROW_STR + seg * 16;

    for (int kt = 0; kt < K; kt += 16) {
        size_t ao = (size_t)(m0 + row) * lda + kt + seg * 8;
        size_t bo = (size_t)(n0 + row) * ldb + kt + seg * 8;
        uint4 a_h = *(const uint4*)(Ah + ao);
        uint4 a_l = *(const uint4*)(Al + ao);
        uint4 b_h = *(const uint4*)(Bh + bo);
        uint4 b_l = *(const uint4*)(Bl + bo);
        *(uint4*)(smem + so)                  = a_h;
        *(uint4*)(smem + TILE_BYTES + so)     = a_l;
        *(uint4*)(smem + 2 * TILE_BYTES + so) = b_h;
        *(uint4*)(smem + 3 * TILE_BYTES + so) = b_l;
        __syncthreads();

        uint32_t ah[2][4], al[2][4];
#pragma unroll
        for (int mt = 0; mt < 2; mt++) {
            uint32_t mrow = wm * 32 + mt * 16 + (lane & 15);
            uint32_t co = (uint32_t)(lane >> 4) << 4;
            ldsm4(ah[mt], sb + mrow * ROW_STR + co);
            ldsm4(al[mt], sb + TILE_BYTES + mrow * ROW_STR + co);
        }
#pragma unroll
        for (int nt2 = 0; nt2 < 4; nt2++) {
            uint32_t brow = wn * 64 + nt2 * 16 + (lane & 7) + ((lane >> 4) << 3);
            uint32_t co = (uint32_t)((lane >> 3) & 1) << 4;
            uint32_t bh[4], bl[4];
            ldsm4(bh, sb + 2 * TILE_BYTES + brow * ROW_STR + co);
            ldsm4(bl, sb + 3 * TILE_BYTES + brow * ROW_STR + co);
#pragma unroll
            for (int mt = 0; mt < 2; mt++) {
#pragma unroll
                for (int hf = 0; hf < 2; hf++) {
                    int nt = nt2 * 2 + hf;
                    mma16816(acc[mt][nt], ah[mt], bh + hf * 2);
                    mma16816(acc[mt][nt], ah[mt], bl + hf * 2);
                    mma16816(acc[mt][nt], al[mt], bh + hf * 2);
                }
            }
        }
        __syncthreads();
    }
}

// ---------------------------------------------------------------------------
// 5) attn[h] = q_s @ k_s^T (R5-proven, verbatim)   grid (16,16,8)
// ---------------------------------------------------------------------------
__global__ __launch_bounds__(256) void attn_mma_kernel(float* __restrict__ outp) {
    __shared__ __align__(16) char smem[CORE_SMEM];
    int h = blockIdx.z;
    int m0 = blockIdx.y * 128, n0 = blockIdx.x * 128;
    size_t hoff = (size_t)h * C_SEQ * D_DIM;

    float acc[2][8][4];
    gemm_hilo_core(acc, g_qh + hoff, g_ql + hoff, D_DIM, m0,
                   g_kh + hoff, g_kl + hoff, D_DIM, n0, D_DIM, smem);

    float* Cp = outp + OUT_OFF + (size_t)h * C_SEQ * C_SEQ;
    int lane = threadIdx.x & 31;
    int wid = threadIdx.x >> 5;
    int wm = wid >> 1, wn = wid & 1;
#pragma unroll
    for (int mt = 0; mt < 2; mt++) {
#pragma unroll
        for (int hf = 0; hf < 2; hf++) {
            int rr = m0 + wm * 32 + mt * 16 + (lane >> 2) + hf * 8;
            float* rowp = Cp + (size_t)rr * C_SEQ;
#pragma unroll
            for (int nt = 0; nt < 8; nt++) {
                int cc = n0 + wn * 64 + nt * 8 + ((lane & 3) << 1);
                *(float2*)(rowp + cc) = make_float2(acc[mt][nt][hf * 2], acc[mt][nt][hf * 2 + 1]);
            }
        }
    }
}

// ---------------------------------------------------------------------------
// 6) ctxT[e''][d] = sum_n v[n][e''] k_s[n][d]  (A=vT, B=kT, K=2048) grid (4,4,8)
//    Output rows e'' (m), cols d (n of GEMM), K-major for out's B operand.
// ---------------------------------------------------------------------------
__global__ __launch_bounds__(256) void ctx_mma_kernel() {
    __shared__ __align__(16) char smem[CORE_SMEM];
    int h = blockIdx.z;
    int m0 = blockIdx.y * 128, n0 = blockIdx.x * 128;  // m0: e'', n0: d
    size_t hoff = (size_t)h * D_DIM * C_SEQ;

    float acc[2][8][4];
    gemm_hilo_core(acc, g_vth + hoff, g_vtl + hoff, C_SEQ, m0,
                   g_kth + hoff, g_ktl + hoff, C_SEQ, n0, C_SEQ, smem);

    int lane = threadIdx.x & 31;
    int wid = threadIdx.x >> 5;
    int wm = wid >> 1, wn = wid & 1;
#pragma unroll
    for (int mt = 0; mt < 2; mt++) {
#pragma unroll
        for (int hf = 0; hf < 2; hf++) {
            int e = m0 + wm * 32 + mt * 16 + (lane >> 2) + hf * 8;
            size_t rowo = ((size_t)h * D_DIM + e) * D_DIM;
#pragma unroll
            for (int nt = 0; nt < 8; nt++) {
                int d = n0 + wn * 64 + nt * 8 + ((lane & 3) << 1);
                __nv_bfloat16 h0, l0, h1, l1;
                split_bf16(acc[mt][nt][hf * 2 + 0], h0, l0);
                split_bf16(acc[mt][nt][hf * 2 + 1], h1, l1);
                g_cth[rowo + d]     = h0;
                g_cth[rowo + d + 1] = h1;
                g_ctl[rowo + d]     = l0;
                g_ctl[rowo + d + 1] = l1;
            }
        }
    }
}

// ---------------------------------------------------------------------------
// 7) out[h] = q_s @ ctx  (A=q hi/lo, B=ctxT hi/lo, K=512) -> final view
//    grid (4,16,8)
// ---------------------------------------------------------------------------
__global__ __launch_bounds__(256) void out_mma_kernel(float* __restrict__ outp) {
    __shared__ __align__(16) char smem[CORE_SMEM];
    int h = blockIdx.z;
    int m0 = blockIdx.y * 128, n0 = blockIdx.x * 128;  // m0: c', n0: d'
    size_t qoff = (size_t)h * C_SEQ * D_DIM;
    size_t coff = (size_t)h * D_DIM * D_DIM;

    float acc[2][8][4];
    gemm_hilo_core(acc, g_qh + qoff, g_ql + qoff, D_DIM, m0,
                   g_cth + coff, g_ctl + coff, D_DIM, n0, D_DIM, smem);

    int lane = threadIdx.x & 31;
    int wid = threadIdx.x >> 5;
    int wm = wid >> 1, wn = wid & 1;
#pragma unroll
    for (int mt = 0; mt < 2; mt++) {
#pragma unroll
        for (int hf = 0; hf < 2; hf++) {
            int cp = m0 + wm * 32 + mt * 16 + (lane >> 2) + hf * 8;
#pragma unroll
            for (int nt = 0; nt < 8; nt++) {
                int dp = n0 + wn * 64 + nt * 8 + ((lane & 3) << 1);
                int r = dp >> 5, e2 = dp & 31;
                float* dst = outp + (size_t)r * (C_SEQ * E_DIM) + (size_t)cp * E_DIM + h * 32 + e2;
                *(float2*)dst = make_float2(acc[mt][nt][hf * 2], acc[mt][nt][hf * 2 + 1]);
            }
        }
    }
}

// ---------------------------------------------------------------------------

extern "C" void kernel_launch(void* const* d_in, const int* in_sizes, int n_in,
                              void* d_out, int out_size) {
    const float* x  = (const float*)d_in[0];
    const float* Wq = (const float*)d_in[1];
    const float* bq = (const float*)d_in[2];
    const float* Wk = (const float*)d_in[3];
    const float* bk = (const float*)d_in[4];
    const float* Wv = (const float*)d_in[5];
    const float* bv = (const float*)d_in[6];
    float* out = (float*)d_out;

    proj_kernel<<<dim3(2, 256, 3), 256>>>(x, Wq, bq, Wk, bk, Wv, bv);
    softmax_q_kernel<<<H_NUM * C_SEQ, 128>>>();
    softmax_k_kernel<<<dim3(16, 8), dim3(32, 8)>>>();
    transpose_hilo_kernel<<<dim3(16, 64, 16), dim3(32, 8)>>>();
    attn_mma_kernel<<<dim3(16, 16, 8), 256>>>(out);
    ctx_mma_kernel<<<dim3(4, 4, 8), 256>>>();
    out_mma_kernel<<<dim3(4, 16, 8), 256>>>(out);
}

// round 9
// speedup vs baseline: 2.1357x; 1.3361x over previous
#include <cuda_runtime.h>
#include <cuda_bf16.h>
#include <cstdint>

// Problem constants
#define C_SEQ   2048
#define E_DIM   256
#define H_NUM   8
#define D_DIM   512                 // R*hd
#define OUT_OFF 8388608ULL          // 16*2048*256 floats (out region size)
#define Q_SCALE 22.627416997969522f // sqrt(512)

// ---------------------------------------------------------------------------
// Device scratch
// ---------------------------------------------------------------------------
__device__ float g_q[H_NUM * C_SEQ * D_DIM];
__device__ float g_k[H_NUM * C_SEQ * D_DIM];
__device__ float g_v[H_NUM * C_SEQ * D_DIM];

__device__ __align__(16) __nv_bfloat16 g_qh[H_NUM * C_SEQ * D_DIM];
__device__ __align__(16) __nv_bfloat16 g_ql[H_NUM * C_SEQ * D_DIM];
__device__ __align__(16) __nv_bfloat16 g_kh[H_NUM * C_SEQ * D_DIM];
__device__ __align__(16) __nv_bfloat16 g_kl[H_NUM * C_SEQ * D_DIM];
__device__ __align__(16) __nv_bfloat16 g_kth[H_NUM * D_DIM * C_SEQ];
__device__ __align__(16) __nv_bfloat16 g_ktl[H_NUM * D_DIM * C_SEQ];
__device__ __align__(16) __nv_bfloat16 g_vth[H_NUM * D_DIM * C_SEQ];
__device__ __align__(16) __nv_bfloat16 g_vtl[H_NUM * D_DIM * C_SEQ];
__device__ __align__(16) __nv_bfloat16 g_cth[H_NUM * D_DIM * D_DIM];  // ctxT[e''][d]
__device__ __align__(16) __nv_bfloat16 g_ctl[H_NUM * D_DIM * D_DIM];

// ---------------------------------------------------------------------------
// Helpers
// ---------------------------------------------------------------------------
__device__ __forceinline__ uint32_t smem_to_u32(const void* p) {
    uint32_t a;
    asm("{ .reg .u64 t; cvta.to.shared.u64 t, %1; cvt.u32.u64 %0, t; }" : "=r"(a) : "l"(p));
    return a;
}
__device__ __forceinline__ void ldsm4(uint32_t r[4], uint32_t addr) {
    asm volatile("ldmatrix.sync.aligned.m8n8.x4.shared.b16 {%0,%1,%2,%3}, [%4];"
        : "=r"(r[0]), "=r"(r[1]), "=r"(r[2]), "=r"(r[3]) : "r"(addr));
}
__device__ __forceinline__ void mma16816(float d[4], const uint32_t a[4], const uint32_t b[2]) {
    asm volatile(
        "mma.sync.aligned.m16n8k16.row.col.f32.bf16.bf16.f32 "
        "{%0,%1,%2,%3}, {%4,%5,%6,%7}, {%8,%9}, {%0,%1,%2,%3};"
        : "+f"(d[0]), "+f"(d[1]), "+f"(d[2]), "+f"(d[3])
        : "r"(a[0]), "r"(a[1]), "r"(a[2]), "r"(a[3]), "r"(b[0]), "r"(b[1]));
}
__device__ __forceinline__ void split_bf16(float x, __nv_bfloat16& h, __nv_bfloat16& l) {
    h = __float2bfloat16_rn(x);
    l = __float2bfloat16_rn(x - __bfloat162float(h));
}
// 8 fp32 -> 8 hi-bf16 (uint4) + 8 lo-bf16 (uint4)
__device__ __forceinline__ void split8(float4 u0, float4 u1, uint4& hi, uint4& lo) {
    float v[8] = {u0.x, u0.y, u0.z, u0.w, u1.x, u1.y, u1.z, u1.w};
    uint32_t h[4], l[4];
#pragma unroll
    for (int i = 0; i < 4; i++) {
        __nv_bfloat16 h0, l0, h1, l1;
        split_bf16(v[2 * i + 0], h0, l0);
        split_bf16(v[2 * i + 1], h1, l1);
        __nv_bfloat162 ph(h0, h1), pl(l0, l1);
        h[i] = *reinterpret_cast<uint32_t*>(&ph);
        l[i] = *reinterpret_cast<uint32_t*>(&pl);
    }
    hi = make_uint4(h[0], h[1], h[2], h[3]);
    lo = make_uint4(l[0], l[1], l[2], l[3]);
}

#define ROW_STR    48
#define TILE_BYTES (128 * ROW_STR)   // 6144
#define CORE_SMEM  (4 * TILE_BYTES)  // 24576

// ---------------------------------------------------------------------------
// hi/lo bf16 HMMA GEMM core (R5/R8-PROVEN — verbatim).
// ---------------------------------------------------------------------------
__device__ __forceinline__ void gemm_hilo_core(
    float acc[2][8][4],
    const __nv_bfloat16* __restrict__ Ah, const __nv_bfloat16* __restrict__ Al,
    int lda, int m0,
    const __nv_bfloat16* __restrict__ Bh, const __nv_bfloat16* __restrict__ Bl,
    int ldb, int n0,
    int K, char* smem) {
    int tid = threadIdx.x;
    int lane = tid & 31;
    int wid = tid >> 5;
    int wm = wid >> 1, wn = wid & 1;
    uint32_t sb = smem_to_u32(smem);

#pragma unroll
    for (int mt = 0; mt < 2; mt++)
#pragma unroll
        for (int nt = 0; nt < 8; nt++)
#pragma unroll
            for (int f = 0; f < 4; f++) acc[mt][nt][f] = 0.f;

    int row = tid >> 1;
    int seg = tid & 1;
    uint32_t so = row * ROW_STR + seg * 16;

    for (int kt = 0; kt < K; kt += 16) {
        size_t ao = (size_t)(m0 + row) * lda + kt + seg * 8;
        size_t bo = (size_t)(n0 + row) * ldb + kt + seg * 8;
        uint4 a_h = *(const uint4*)(Ah + ao);
        uint4 a_l = *(const uint4*)(Al + ao);
        uint4 b_h = *(const uint4*)(Bh + bo);
        uint4 b_l = *(const uint4*)(Bl + bo);
        *(uint4*)(smem + so)                  = a_h;
        *(uint4*)(smem + TILE_BYTES + so)     = a_l;
        *(uint4*)(smem + 2 * TILE_BYTES + so) = b_h;
        *(uint4*)(smem + 3 * TILE_BYTES + so) = b_l;
        __syncthreads();

        uint32_t ah[2][4], al[2][4];
#pragma unroll
        for (int mt = 0; mt < 2; mt++) {
            uint32_t mrow = wm * 32 + mt * 16 + (lane & 15);
            uint32_t co = (uint32_t)(lane >> 4) << 4;
            ldsm4(ah[mt], sb + mrow * ROW_STR + co);
            ldsm4(al[mt], sb + TILE_BYTES + mrow * ROW_STR + co);
        }
#pragma unroll
        for (int nt2 = 0; nt2 < 4; nt2++) {
            uint32_t brow = wn * 64 + nt2 * 16 + (lane & 7) + ((lane >> 4) << 3);
            uint32_t co = (uint32_t)((lane >> 3) & 1) << 4;
            uint32_t bh[4], bl[4];
            ldsm4(bh, sb + 2 * TILE_BYTES + brow * ROW_STR + co);
            ldsm4(bl, sb + 3 * TILE_BYTES + brow * ROW_STR + co);
#pragma unroll
            for (int mt = 0; mt < 2; mt++) {
#pragma unroll
                for (int hf = 0; hf < 2; hf++) {
                    int nt = nt2 * 2 + hf;
                    mma16816(acc[mt][nt], ah[mt], bh + hf * 2);
                    mma16816(acc[mt][nt], ah[mt], bl + hf * 2);
                    mma16816(acc[mt][nt], al[mt], bh + hf * 2);
                }
            }
        }
        __syncthreads();
    }
}

// ---------------------------------------------------------------------------
// 1) Projections via MMA with FUSED fp32->hi/lo conversion in the loader.
//    Same sync-core structure; sources are fp32 x and W. grid (2,256,3).
// ---------------------------------------------------------------------------
__global__ __launch_bounds__(256) void proj_mma_kernel(
    const float* __restrict__ x,
    const float* __restrict__ Wq, const float* __restrict__ bq,
    const float* __restrict__ Wk, const float* __restrict__ bk,
    const float* __restrict__ Wv, const float* __restrict__ bv) {
    __shared__ __align__(16) char smem[CORE_SMEM];
    int z = blockIdx.z;
    const float* W = (z == 0) ? Wq : (z == 1) ? Wk : Wv;
    const float* b = (z == 0) ? bq : (z == 1) ? bk : bv;
    float* dst = (z == 0) ? g_q : (z == 1) ? g_k : g_v;
    int m0 = blockIdx.y * 128, n0 = blockIdx.x * 128;

    int tid = threadIdx.x;
    int lane = tid & 31;
    int wid = tid >> 5;
    int wm = wid >> 1, wn = wid & 1;
    uint32_t sb = smem_to_u32(smem);

    float acc[2][8][4];
#pragma unroll
    for (int mt = 0; mt < 2; mt++)
#pragma unroll
        for (int nt = 0; nt < 8; nt++)
#pragma unroll
            for (int f = 0; f < 4; f++) acc[mt][nt][f] = 0.f;

    int row = tid >> 1;
    int seg = tid & 1;
    uint32_t so = row * ROW_STR + seg * 16;

    for (int kt = 0; kt < E_DIM; kt += 16) {
        const float* ax = x + (size_t)(m0 + row) * E_DIM + kt + seg * 8;
        const float* bx = W + (size_t)(n0 + row) * E_DIM + kt + seg * 8;
        float4 a0 = *(const float4*)(ax);
        float4 a1 = *(const float4*)(ax + 4);
        float4 b0 = *(const float4*)(bx);
        float4 b1 = *(const float4*)(bx + 4);
        uint4 ahv, alv, bhv, blv;
        split8(a0, a1, ahv, alv);
        split8(b0, b1, bhv, blv);
        *(uint4*)(smem + so)                  = ahv;
        *(uint4*)(smem + TILE_BYTES + so)     = alv;
        *(uint4*)(smem + 2 * TILE_BYTES + so) = bhv;
        *(uint4*)(smem + 3 * TILE_BYTES + so) = blv;
        __syncthreads();

        uint32_t ah[2][4], al[2][4];
#pragma unroll
        for (int mt = 0; mt < 2; mt++) {
            uint32_t mrow = wm * 32 + mt * 16 + (lane & 15);
            uint32_t co = (uint32_t)(lane >> 4) << 4;
            ldsm4(ah[mt], sb + mrow * ROW_STR + co);
            ldsm4(al[mt], sb + TILE_BYTES + mrow * ROW_STR + co);
        }
#pragma unroll
        for (int nt2 = 0; nt2 < 4; nt2++) {
            uint32_t brow = wn * 64 + nt2 * 16 + (lane & 7) + ((lane >> 4) << 3);
            uint32_t co = (uint32_t)((lane >> 3) & 1) << 4;
            uint32_t bh[4], bl[4];
            ldsm4(bh, sb + 2 * TILE_BYTES + brow * ROW_STR + co);
            ldsm4(bl, sb + 3 * TILE_BYTES + brow * ROW_STR + co);
#pragma unroll
            for (int mt = 0; mt < 2; mt++) {
#pragma unroll
                for (int hf = 0; hf < 2; hf++) {
                    int nt = nt2 * 2 + hf;
                    mma16816(acc[mt][nt], ah[mt], bh + hf * 2);
                    mma16816(acc[mt][nt], ah[mt], bl + hf * 2);
                    mma16816(acc[mt][nt], al[mt], bh + hf * 2);
                }
            }
        }
        __syncthreads();
    }

    // epilogue: bias + scatter into heads layout (fp32), proven mapping
#pragma unroll
    for (int mt = 0; mt < 2; mt++) {
#pragma unroll
        for (int hf = 0; hf < 2; hf++) {
            int gi = m0 + wm * 32 + mt * 16 + (lane >> 2) + hf * 8;
            int r = gi >> 11;
            int c = gi & 2047;
            int hp = c >> 8;
            int cbase = (c & 255) << 3;
#pragma unroll
            for (int nt = 0; nt < 8; nt++) {
                int gj = n0 + wn * 64 + nt * 8 + ((lane & 3) << 1);
                int hh = gj >> 5, e = gj & 31;
                float v0 = acc[mt][nt][hf * 2 + 0] + b[gj];
                float v1 = acc[mt][nt][hf * 2 + 1] + b[gj + 1];
                size_t o = ((size_t)(hp * C_SEQ + (cbase | hh))) * D_DIM + ((r << 5) | e);
                *(float2*)(dst + o) = make_float2(v0, v1);
            }
        }
    }
}

// ---------------------------------------------------------------------------
// 2) Row softmax on q (R8-proven, verbatim)
// ---------------------------------------------------------------------------
__global__ __launch_bounds__(128) void softmax_q_kernel() {
    size_t row = blockIdx.x;
    float4* p = (float4*)(g_q + row * D_DIM);
    int tid = threadIdx.x;
    float4 v = p[tid];

    float m = fmaxf(fmaxf(v.x, v.y), fmaxf(v.z, v.w));
#pragma unroll
    for (int o = 16; o; o >>= 1) m = fmaxf(m, __shfl_xor_sync(0xffffffffu, m, o));
    __shared__ float sm[4];
    __shared__ float ss[4];
    if ((tid & 31) == 0) sm[tid >> 5] = m;
    __syncthreads();
    m = fmaxf(fmaxf(sm[0], sm[1]), fmaxf(sm[2], sm[3]));

    v.x = __expf(v.x - m); v.y = __expf(v.y - m);
    v.z = __expf(v.z - m); v.w = __expf(v.w - m);
    float s = v.x + v.y + v.z + v.w;
#pragma unroll
    for (int o = 16; o; o >>= 1) s += __shfl_xor_sync(0xffffffffu, s, o);
    if ((tid & 31) == 0) ss[tid >> 5] = s;
    __syncthreads();
    s = ss[0] + ss[1] + ss[2] + ss[3];

    float f = Q_SCALE / s;
    v.x *= f; v.y *= f; v.z *= f; v.w *= f;
    p[tid] = v;

    float w[4] = {v.x, v.y, v.z, v.w};
    size_t base = row * D_DIM + tid * 4;
#pragma unroll
    for (int i = 0; i < 4; i++) {
        __nv_bfloat16 hi, lo;
        split_bf16(w[i], hi, lo);
        g_qh[base + i] = hi;
        g_ql[base + i] = lo;
    }
}

// ---------------------------------------------------------------------------
// 3) Column softmax on k (R8-proven, verbatim)
// ---------------------------------------------------------------------------
__global__ void softmax_k_kernel() {
    int h  = blockIdx.y;
    int d0 = blockIdx.x * 32;
    size_t hoff = (size_t)h * C_SEQ * D_DIM;
    float* base = g_k + hoff + d0;
    int tx = threadIdx.x, ty = threadIdx.y;
    __shared__ float red[8][32];

    float m = -1e30f;
    for (int n = ty; n < C_SEQ; n += 8)
        m = fmaxf(m, base[(size_t)n * D_DIM + tx]);
    red[ty][tx] = m;
    __syncthreads();
    if (ty == 0) {
        float t = red[0][tx];
#pragma unroll
        for (int i = 1; i < 8; i++) t = fmaxf(t, red[i][tx]);
        red[0][tx] = t;
    }
    __syncthreads();
    m = red[0][tx];
    __syncthreads();

    float s = 0.f;
    for (int n = ty; n < C_SEQ; n += 8)
        s += __expf(base[(size_t)n * D_DIM + tx] - m);
    red[ty][tx] = s;
    __syncthreads();
    if (ty == 0) {
        float t = red[0][tx];
#pragma unroll
        for (int i = 1; i < 8; i++) t += red[i][tx];
        red[0][tx] = t;
    }
    __syncthreads();
    float inv = 1.f / red[0][tx];

    for (int n = ty; n < C_SEQ; n += 8) {
        size_t idx = (size_t)n * D_DIM + tx;
        float val = __expf(base[idx] - m) * inv;
        base[idx] = val;
        __nv_bfloat16 hi, lo;
        split_bf16(val, hi, lo);
        g_kh[hoff + d0 + idx] = hi;
        g_kl[hoff + d0 + idx] = lo;
    }
}

// ---------------------------------------------------------------------------
// 4) Transpose fp32 [h][2048][512] -> bf16 hi/lo [h][512][2048] (R8-proven)
// ---------------------------------------------------------------------------
__global__ __launch_bounds__(256) void transpose_hilo_kernel() {
    __shared__ float t[32][33];
    int z = blockIdx.z;
    int h = z & 7;
    const float* src = (z < 8) ? g_k : g_v;
    __nv_bfloat16* dh = (z < 8) ? g_kth : g_vth;
    __nv_bfloat16* dl = (z < 8) ? g_ktl : g_vtl;

    int d0 = blockIdx.x * 32;
    int n0 = blockIdx.y * 32;
    int tx = threadIdx.x, ty = threadIdx.y;
    const float* s = src + (size_t)h * C_SEQ * D_DIM;

#pragma unroll
    for (int i = 0; i < 4; i++) {
        int nn = ty + i * 8;
        t[nn][tx] = s[(size_t)(n0 + nn) * D_DIM + d0 + tx];
    }
    __syncthreads();
#pragma unroll
    for (int i = 0; i < 4; i++) {
        int dd = ty + i * 8;
        float val = t[tx][dd];
        __nv_bfloat16 hi, lo;
        split_bf16(val, hi, lo);
        size_t o = ((size_t)h * D_DIM + d0 + dd) * C_SEQ + n0 + tx;
        dh[o] = hi;
        dl[o] = lo;
    }
}

// ---------------------------------------------------------------------------
// 5) attn[h] = q_s @ k_s^T (R8-proven, verbatim)   grid (16,16,8)
// ---------------------------------------------------------------------------
__global__ __launch_bounds__(256) void attn_mma_kernel(float* __restrict__ outp) {
    __shared__ __align__(16) char smem[CORE_SMEM];
    int h = blockIdx.z;
    int m0 = blockIdx.y * 128, n0 = blockIdx.x * 128;
    size_t hoff = (size_t)h * C_SEQ * D_DIM;

    float acc[2][8][4];
    gemm_hilo_core(acc, g_qh + hoff, g_ql + hoff, D_DIM, m0,
                   g_kh + hoff, g_kl + hoff, D_DIM, n0, D_DIM, smem);

    float* Cp = outp + OUT_OFF + (size_t)h * C_SEQ * C_SEQ;
    int lane = threadIdx.x & 31;
    int wid = threadIdx.x >> 5;
    int wm = wid >> 1, wn = wid & 1;
#pragma unroll
    for (int mt = 0; mt < 2; mt++) {
#pragma unroll
        for (int hf = 0; hf < 2; hf++) {
            int rr = m0 + wm * 32 + mt * 16 + (lane >> 2) + hf * 8;
            float* rowp = Cp + (size_t)rr * C_SEQ;
#pragma unroll
            for (int nt = 0; nt < 8; nt++) {
                int cc = n0 + wn * 64 + nt * 8 + ((lane & 3) << 1);
                *(float2*)(rowp + cc) = make_float2(acc[mt][nt][hf * 2], acc[mt][nt][hf * 2 + 1]);
            }
        }
    }
}

// ---------------------------------------------------------------------------
// 6) ctxT[e''][d] = sum_n v[n][e''] k_s[n][d]  (R8-proven)   grid (4,4,8)
// ---------------------------------------------------------------------------
__global__ __launch_bounds__(256) void ctx_mma_kernel() {
    __shared__ __align__(16) char smem[CORE_SMEM];
    int h = blockIdx.z;
    int m0 = blockIdx.y * 128, n0 = blockIdx.x * 128;  // m0: e'', n0: d
    size_t hoff = (size_t)h * D_DIM * C_SEQ;

    float acc[2][8][4];
    gemm_hilo_core(acc, g_vth + hoff, g_vtl + hoff, C_SEQ, m0,
                   g_kth + hoff, g_ktl + hoff, C_SEQ, n0, C_SEQ, smem);

    int lane = threadIdx.x & 31;
    int wid = threadIdx.x >> 5;
    int wm = wid >> 1, wn = wid & 1;
#pragma unroll
    for (int mt = 0; mt < 2; mt++) {
#pragma unroll
        for (int hf = 0; hf < 2; hf++) {
            int e = m0 + wm * 32 + mt * 16 + (lane >> 2) + hf * 8;
            size_t rowo = ((size_t)h * D_DIM + e) * D_DIM;
#pragma unroll
            for (int nt = 0; nt < 8; nt++) {
                int d = n0 + wn * 64 + nt * 8 + ((lane & 3) << 1);
                __nv_bfloat16 h0, l0, h1, l1;
                split_bf16(acc[mt][nt][hf * 2 + 0], h0, l0);
                split_bf16(acc[mt][nt][hf * 2 + 1], h1, l1);
                g_cth[rowo + d]     = h0;
                g_cth[rowo + d + 1] = h1;
                g_ctl[rowo + d]     = l0;
                g_ctl[rowo + d + 1] = l1;
            }
        }
    }
}

// ---------------------------------------------------------------------------
// 7) out[h] = q_s @ ctx (R8-proven)   grid (4,16,8)
// ---------------------------------------------------------------------------
__global__ __launch_bounds__(256) void out_mma_kernel(float* __restrict__ outp) {
    __shared__ __align__(16) char smem[CORE_SMEM];
    int h = blockIdx.z;
    int m0 = blockIdx.y * 128, n0 = blockIdx.x * 128;  // m0: c', n0: d'
    size_t qoff = (size_t)h * C_SEQ * D_DIM;
    size_t coff = (size_t)h * D_DIM * D_DIM;

    float acc[2][8][4];
    gemm_hilo_core(acc, g_qh + qoff, g_ql + qoff, D_DIM, m0,
                   g_cth + coff, g_ctl + coff, D_DIM, n0, D_DIM, smem);

    int lane = threadIdx.x & 31;
    int wid = threadIdx.x >> 5;
    int wm = wid >> 1, wn = wid & 1;
#pragma unroll
    for (int mt = 0; mt < 2; mt++) {
#pragma unroll
        for (int hf = 0; hf < 2; hf++) {
            int cp = m0 + wm * 32 + mt * 16 + (lane >> 2) + hf * 8;
#pragma unroll
            for (int nt = 0; nt < 8; nt++) {
                int dp = n0 + wn * 64 + nt * 8 + ((lane & 3) << 1);
                int r = dp >> 5, e2 = dp & 31;
                float* dst = outp + (size_t)r * (C_SEQ * E_DIM) + (size_t)cp * E_DIM + h * 32 + e2;
                *(float2*)dst = make_float2(acc[mt][nt][hf * 2], acc[mt][nt][hf * 2 + 1]);
            }
        }
    }
}

// ---------------------------------------------------------------------------

extern "C" void kernel_launch(void* const* d_in, const int* in_sizes, int n_in,
                              void* d_out, int out_size) {
    const float* x  = (const float*)d_in[0];
    const float* Wq = (const float*)d_in[1];
    const float* bq = (const float*)d_in[2];
    const float* Wk = (const float*)d_in[3];
    const float* bk = (const float*)d_in[4];
    const float* Wv = (const float*)d_in[5];
    const float* bv = (const float*)d_in[6];
    float* out = (float*)d_out;

    proj_mma_kernel<<<dim3(2, 256, 3), 256>>>(x, Wq, bq, Wk, bk, Wv, bv);
    softmax_q_kernel<<<H_NUM * C_SEQ, 128>>>();
    softmax_k_kernel<<<dim3(16, 8), dim3(32, 8)>>>();
    transpose_hilo_kernel<<<dim3(16, 64, 16), dim3(32, 8)>>>();
    attn_mma_kernel<<<dim3(16, 16, 8), 256>>>(out);
    ctx_mma_kernel<<<dim3(4, 4, 8), 256>>>();
    out_mma_kernel<<<dim3(4, 16, 8), 256>>>(out);
}